// round 13
// baseline (speedup 1.0000x reference)
#include <cuda_runtime.h>
#include <cstdint>

#define L_SEQ 4096
#define BATCH 256
#define NORD  64
#define TCH   32
#define CCH   128   // L_SEQ / TCH
#define BS3   128   // batch half per phase-3 CTA

typedef unsigned long long ull;

__device__ __forceinline__ ull bcast2(float a) {
    ull r; asm("mov.b64 %0, {%1, %1};" : "=l"(r) : "f"(a)); return r;
}
__device__ __forceinline__ void ffma2(ull &d, ull a, ull b) {
    asm("fma.rn.f32x2 %0, %1, %2, %0;" : "+l"(d) : "l"(a), "l"(b));
}
__device__ __forceinline__ float2 unpack2(ull v) {
    float2 f; asm("mov.b64 {%0, %1}, %2;" : "=f"(f.x), "=f"(f.y) : "l"(v)); return f;
}

// Scratch (static device globals: no allocations allowed)
__device__ float g_P[(size_t)CCH * NORD * NORD];   // [c][i][j]  row-major P_c   2 MB
__device__ float g_S[(size_t)CCH * BATCH * NORD];  // [c][b][i]  chunk sources   8 MB
__device__ float g_X[(size_t)CCH * BATCH * NORD];  // [c][b][i]  boundary states 8 MB

// ---------------------------------------------------------------------------
// Phase 1: per chunk c (backward over t, Pt starts as Identity):
//   w_t = (Prod_{tau>t} A_tau) B_t ;  P_c = Prod_t A_t ; S_c = sum w_t u_t.
// NEW: A staged DUPLICATED in smem (Asd[k][2j],[2j+1] = A[k][j]) so the
// matmul FFMA2 reads (a,a) pairs directly -> ZERO broadcast MOVs per k.
// ---------------------------------------------------------------------------
#define P1_DPAD 132
#define P1_SMEM ((NORD * NORD + NORD * P1_DPAD + TCH * NORD + NORD) * 4)

__global__ __launch_bounds__(256) void phase1_kernel(
    const float* __restrict__ A, const float* __restrict__ Bv,
    const float* __restrict__ inp)
{
    extern __shared__ float sm1[];
    float* Pt  = sm1;                      // [64*64] transposed P
    float* Asd = Pt + NORD * NORD;         // [64][132] dup A
    float* W   = Asd + NORD * P1_DPAD;     // [TCH][64]
    float* Bs  = W + TCH * NORD;           // [64]

    const int c = blockIdx.x, tid = threadIdx.x;
    const int t0 = c * TCH;
    const int ri = (tid & 15) * 4;   // i-tile
    const int cj = (tid >> 4) * 4;   // j-tile

    // init: Pt = Identity; stage dup-A and B for t = TCH-1
    for (int idx = tid; idx < NORD * NORD; idx += 256)
        Pt[idx] = ((idx >> 6) == (idx & 63)) ? 1.f : 0.f;
    {
        const float4* A4 = (const float4*)(A + (size_t)(t0 + TCH - 1) * (NORD * NORD));
        #pragma unroll
        for (int q = 0; q < 4; q++) {
            int f = tid + q * 256;
            int k = f >> 4, j0 = (f & 15) * 4;
            float4 v = A4[f];
            float* row = Asd + k * P1_DPAD + 2 * j0;
            row[0] = v.x; row[1] = v.x; row[2] = v.y; row[3] = v.y;
            row[4] = v.z; row[5] = v.z; row[6] = v.w; row[7] = v.w;
        }
        if (tid < 64) Bs[tid] = Bv[(size_t)(t0 + TCH - 1) * NORD + tid];
    }
    __syncthreads();

    #pragma unroll 1
    for (int t = TCH - 1; t >= 0; --t) {
        // prefetch next (earlier) A and B into registers
        float4 apf0, apf1, apf2, apf3; float bpf;
        if (t > 0) {
            const float4* An = (const float4*)(A + (size_t)(t0 + t - 1) * (NORD * NORD));
            apf0 = An[tid]; apf1 = An[tid + 256]; apf2 = An[tid + 512]; apf3 = An[tid + 768];
            if (tid < 64) bpf = Bv[(size_t)(t0 + t - 1) * NORD + tid];
        }

        // w_t[i] = sum_k Pt[k][i]*B_t[k]  (P BEFORE update => suffix), 4 chains
        float w0 = 0.f, w1 = 0.f, w2 = 0.f, w3 = 0.f;
        if (tid < NORD) {
            #pragma unroll
            for (int k4 = 0; k4 < 16; k4++) {
                w0 += Pt[(4 * k4 + 0) * NORD + tid] * Bs[4 * k4 + 0];
                w1 += Pt[(4 * k4 + 1) * NORD + tid] * Bs[4 * k4 + 1];
                w2 += Pt[(4 * k4 + 2) * NORD + tid] * Bs[4 * k4 + 2];
                w3 += Pt[(4 * k4 + 3) * NORD + tid] * Bs[4 * k4 + 3];
            }
        }

        // Qt[j][i] = sum_k Pt[k][i] * A_t[k][j]  (P <- P @ A_t, kept transposed)
        ull acc2[4][2];
        #pragma unroll
        for (int jj = 0; jj < 4; jj++) { acc2[jj][0] = 0ull; acc2[jj][1] = 0ull; }

        #pragma unroll 8
        for (int k = 0; k < NORD; k++) {
            ulonglong2 p  = *(const ulonglong2*)&Pt[k * NORD + ri];
            ulonglong2 a0 = *(const ulonglong2*)&Asd[k * P1_DPAD + 2 * cj];
            ulonglong2 a1 = *(const ulonglong2*)&Asd[k * P1_DPAD + 2 * cj + 4];
            ffma2(acc2[0][0], a0.x, p.x); ffma2(acc2[0][1], a0.x, p.y);
            ffma2(acc2[1][0], a0.y, p.x); ffma2(acc2[1][1], a0.y, p.y);
            ffma2(acc2[2][0], a1.x, p.x); ffma2(acc2[2][1], a1.x, p.y);
            ffma2(acc2[3][0], a1.y, p.x); ffma2(acc2[3][1], a1.y, p.y);
        }
        __syncthreads();           // done reading Pt, Asd, Bs

        if (tid < NORD) W[t * NORD + tid] = (w0 + w1) + (w2 + w3);
        if (t > 0) {
            #pragma unroll
            for (int jj = 0; jj < 4; jj++)
                *(ulonglong2*)&Pt[(cj + jj) * NORD + ri] =
                    make_ulonglong2(acc2[jj][0], acc2[jj][1]);
            #pragma unroll
            for (int q = 0; q < 4; q++) {
                int f = tid + q * 256;
                int k = f >> 4, j0 = (f & 15) * 4;
                float4 v = (q == 0) ? apf0 : (q == 1) ? apf1 : (q == 2) ? apf2 : apf3;
                float* row = Asd + k * P1_DPAD + 2 * j0;
                row[0] = v.x; row[1] = v.x; row[2] = v.y; row[3] = v.y;
                row[4] = v.z; row[5] = v.z; row[6] = v.w; row[7] = v.w;
            }
            if (tid < 64) Bs[tid] = bpf;
        } else {
            // final product: write g_P[c] row-major [i][j] straight from registers
            float f[4][4];
            #pragma unroll
            for (int jj = 0; jj < 4; jj++) {
                float2 v0 = unpack2(acc2[jj][0]); f[jj][0] = v0.x; f[jj][1] = v0.y;
                float2 v1 = unpack2(acc2[jj][1]); f[jj][2] = v1.x; f[jj][3] = v1.y;
            }
            float* gp = g_P + (size_t)c * (NORD * NORD);
            #pragma unroll
            for (int ii = 0; ii < 4; ii++)
                *(float4*)&gp[(ri + ii) * NORD + cj] =
                    make_float4(f[0][ii], f[1][ii], f[2][ii], f[3][ii]);
        }
        __syncthreads();
    }

    // S_c[b][i] = sum_t W[t][i] * inputs[t0+t][b]   (thread = batch b)
    {
        float u[TCH];
        #pragma unroll
        for (int tt = 0; tt < TCH; tt++) u[tt] = inp[(size_t)(t0 + tt) * BATCH + tid];
        float* sp = g_S + ((size_t)c * BATCH + tid) * NORD;
        #pragma unroll
        for (int half = 0; half < 2; half++) {
            ull acc[16];
            #pragma unroll
            for (int m = 0; m < 16; m++) acc[m] = 0ull;
            #pragma unroll 4
            for (int tt = 0; tt < TCH; tt++) {
                ull ub = bcast2(u[tt]);
                const ull* wrow = (const ull*)&W[tt * NORD + half * 32];
                #pragma unroll
                for (int m = 0; m < 16; m++) ffma2(acc[m], ub, wrow[m]);
            }
            #pragma unroll
            for (int m2 = 0; m2 < 8; m2++)
                *(ulonglong2*)&sp[half * 32 + m2 * 4] =
                    make_ulonglong2(acc[2 * m2], acc[2 * m2 + 1]);
        }
    }
}

// ---------------------------------------------------------------------------
// Phase 2 (unchanged): X_c = P_c @ X_{c-1} + S_c
// ---------------------------------------------------------------------------
#define P2PAD 68
__global__ __launch_bounds__(256) void phase2_kernel()
{
    __shared__ float Ps[2][NORD * P2PAD];
    __shared__ float xsm[2][4][NORD];

    const int tid = threadIdx.x;
    const int b0 = blockIdx.x * 4;
    const int i  = tid >> 2;
    const int bb = tid & 3;

    {
        const float4* gp = (const float4*)g_P;
        #pragma unroll
        for (int q = 0; q < 4; q++) {
            int f = tid + q * 256;
            int ii = f >> 4, j4 = f & 15;
            *(float4*)&Ps[0][ii * P2PAD + j4 * 4] = gp[f];
        }
        xsm[0][bb][i] = 0.f;
    }
    float s_cur = g_S[((size_t)b0 + bb) * NORD + i];
    __syncthreads();

    int cur = 0;
    #pragma unroll 1
    for (int c = 0; c < CCH; c++) {
        float4 pf0, pf1, pf2, pf3; float s_nxt = 0.f;
        if (c + 1 < CCH) {
            const float4* gp = (const float4*)(g_P + (size_t)(c + 1) * (NORD * NORD));
            pf0 = gp[tid]; pf1 = gp[tid + 256]; pf2 = gp[tid + 512]; pf3 = gp[tid + 768];
            s_nxt = g_S[((size_t)(c + 1) * BATCH + b0 + bb) * NORD + i];
        }

        ull a0 = 0ull, a1 = 0ull, a2 = 0ull, a3 = 0ull;
        const float* prow = &Ps[cur][i * P2PAD];
        const float* xrow = &xsm[cur][bb][0];
        #pragma unroll
        for (int j8 = 0; j8 < 8; j8++) {
            ulonglong2 p0 = *(const ulonglong2*)(prow + j8 * 8);
            ulonglong2 p1 = *(const ulonglong2*)(prow + j8 * 8 + 4);
            ulonglong2 x0 = *(const ulonglong2*)(xrow + j8 * 8);
            ulonglong2 x1 = *(const ulonglong2*)(xrow + j8 * 8 + 4);
            ffma2(a0, p0.x, x0.x); ffma2(a1, p0.y, x0.y);
            ffma2(a2, p1.x, x1.x); ffma2(a3, p1.y, x1.y);
        }
        float2 f0 = unpack2(a0), f1 = unpack2(a1), f2 = unpack2(a2), f3 = unpack2(a3);
        float acc = s_cur + ((f0.x + f0.y) + (f1.x + f1.y)) + ((f2.x + f2.y) + (f3.x + f3.y));

        const int nxt = cur ^ 1;
        xsm[nxt][bb][i] = acc;
        g_X[((size_t)c * BATCH + b0 + bb) * NORD + i] = acc;
        if (c + 1 < CCH) {
            #pragma unroll
            for (int q = 0; q < 4; q++) {
                float4 pv = (q == 0) ? pf0 : (q == 1) ? pf1 : (q == 2) ? pf2 : pf3;
                int f = tid + q * 256;
                int ii = f >> 4, j4 = f & 15;
                *(float4*)&Ps[nxt][ii * P2PAD + j4 * 4] = pv;
            }
        }
        s_cur = s_nxt;
        __syncthreads();
        cur = nxt;
    }
}

// ---------------------------------------------------------------------------
// Phase 3: 2 CTAs per chunk (batch halves), 256 threads, 2 CTAs/SM.
// NEW: A staged DUP-PERMUTED:  Ad[k][2*perm(i)+h] = A[i][k], perm(i) =
// (i&7)*8 + (i>>3).  Warp riq's 8 interleaved rows {riq+8m} sit at dup
// positions [16riq, 16riq+16): 4 broadcast LDS.128 per k give (a,a) pairs
// directly -> ZERO MOVs in the hot loop (was 16 MOVs per k).
// Lower-triangular A: row riq+8m active for k <= riq+8m (warp-uniform blocks).
// ---------------------------------------------------------------------------
#define P3_DPAD 132
#define P3_SMEM ((2 * NORD * P3_DPAD + NORD * BS3 + 2 * 2 * NORD) * 4)

__device__ __forceinline__ void p3_stage_AB(float* Ad, float* Bsd,
                                            const float4* apf, float4 bpf, int tid) {
    #pragma unroll
    for (int q = 0; q < 4; q++) {
        int f = tid + q * 256;              // float4 idx: i = f>>4, j = 4*(f&15)
        int i = f >> 4, j0 = (f & 15) * 4;
        int p2 = (((i & 7) << 3) | (i >> 3)) * 2;   // dup-permuted position
        float4 v = apf[q];
        float* c0 = Ad + (j0 + 0) * P3_DPAD + p2;
        float* c1 = Ad + (j0 + 1) * P3_DPAD + p2;
        float* c2 = Ad + (j0 + 2) * P3_DPAD + p2;
        float* c3 = Ad + (j0 + 3) * P3_DPAD + p2;
        c0[0] = v.x; c0[1] = v.x;
        c1[0] = v.y; c1[1] = v.y;
        c2[0] = v.z; c2[1] = v.z;
        c3[0] = v.w; c3[1] = v.w;
    }
    if (tid < 16) {
        #pragma unroll
        for (int r = 0; r < 4; r++) {
            int i = 4 * tid + r;
            int p2 = (((i & 7) << 3) | (i >> 3)) * 2;
            float v = (r == 0) ? bpf.x : (r == 1) ? bpf.y : (r == 2) ? bpf.z : bpf.w;
            Bsd[p2] = v; Bsd[p2 + 1] = v;
        }
    }
}

__global__ __launch_bounds__(256, 2) void phase3_kernel(
    const float* __restrict__ A, const float* __restrict__ Bv,
    const float* __restrict__ inp, float* __restrict__ out)
{
    extern __shared__ float sm[];
    float* Ad  = sm;                          // [2][64][132] dup-permuted A
    float* xs  = sm + 2 * NORD * P3_DPAD;     // [64][128]    xs[j][b]
    float* Bsd = xs + NORD * BS3;             // [2][128]     dup-permuted B

    const int tid = threadIdx.x;
    const int c   = blockIdx.x >> 1;
    const int b0  = (blockIdx.x & 1) * BS3;
    const int t0  = c * TCH;
    const int riq = tid >> 5;                 // warp-uniform row offset 0..7
    const int bq  = (tid & 31) * 4;           // 4 batches per thread

    // stage A,B for t=0; load u for t=0
    {
        const float4* A4 = (const float4*)(A + (size_t)t0 * (NORD * NORD));
        float4 apf[4];
        #pragma unroll
        for (int q = 0; q < 4; q++) apf[q] = A4[tid + q * 256];
        float4 bpf = make_float4(0.f, 0.f, 0.f, 0.f);
        if (tid < 16) bpf = ((const float4*)(Bv + (size_t)t0 * NORD))[tid];
        p3_stage_AB(Ad, Bsd, apf, bpf, tid);
    }
    ulonglong2 ucur = *(const ulonglong2*)(inp + (size_t)t0 * BATCH + b0 + bq);

    // load initial state into xs[j][b]: thread = (bcol = tid&127, jhalf = tid>>7)
    {
        const int bcol = tid & 127, jhalf = tid >> 7;
        if (c == 0) {
            #pragma unroll
            for (int j = 0; j < 32; j++) xs[(jhalf * 32 + j) * BS3 + bcol] = 0.f;
        } else {
            const float4* Xp = (const float4*)(g_X + (((size_t)(c - 1)) * BATCH + b0 + bcol) * NORD + jhalf * 32);
            #pragma unroll
            for (int j4 = 0; j4 < 8; j4++) {
                float4 v = Xp[j4];
                xs[(jhalf * 32 + 4 * j4 + 0) * BS3 + bcol] = v.x;
                xs[(jhalf * 32 + 4 * j4 + 1) * BS3 + bcol] = v.y;
                xs[(jhalf * 32 + 4 * j4 + 2) * BS3 + bcol] = v.z;
                xs[(jhalf * 32 + 4 * j4 + 3) * BS3 + bcol] = v.w;
            }
        }
    }
    __syncthreads();

    int cur = 0;
    #pragma unroll 1
    for (int t = 0; t < TCH; t++) {
        // prefetch next A,B,u into registers
        float4 apf[4]; float4 bpf; ulonglong2 unxt;
        if (t < TCH - 1) {
            const float4* An = (const float4*)(A + (size_t)(t0 + t + 1) * (NORD * NORD));
            #pragma unroll
            for (int q = 0; q < 4; q++) apf[q] = An[tid + q * 256];
            if (tid < 16) bpf = ((const float4*)(Bv + (size_t)(t0 + t + 1) * NORD))[tid];
            unxt = *(const ulonglong2*)(inp + (size_t)(t0 + t + 1) * BATCH + b0 + bq);
        }

        const float* Ac = Ad + cur * (NORD * P3_DPAD);
        const float* Bc = Bsd + cur * (2 * NORD);

        // init acc[m] = B[row]*u   (dup pairs from Bsd, zero MOV)
        ull acc[8][2];
        {
            const float* brow = Bc + 16 * riq;
            ulonglong2 Bp0 = *(const ulonglong2*)(brow);
            ulonglong2 Bp1 = *(const ulonglong2*)(brow + 4);
            ulonglong2 Bp2 = *(const ulonglong2*)(brow + 8);
            ulonglong2 Bp3 = *(const ulonglong2*)(brow + 12);
            ull bb[8] = {Bp0.x, Bp0.y, Bp1.x, Bp1.y, Bp2.x, Bp2.y, Bp3.x, Bp3.y};
            #pragma unroll
            for (int m = 0; m < 8; m++) {
                acc[m][0] = 0ull; acc[m][1] = 0ull;
                ffma2(acc[m][0], bb[m], ucur.x); ffma2(acc[m][1], bb[m], ucur.y);
            }
        }

        // triangular MACs: row riq+8m active for k <= riq+8m
        #define P3_ACCK(K, MSTART)                                              \
        {                                                                       \
            ulonglong2 X = *(const ulonglong2*)&xs[(K) * BS3 + bq];             \
            const float* arow = Ac + (K) * P3_DPAD + 16 * riq;                  \
            ull ap[8];                                                          \
            if ((MSTART) < 2) {                                                 \
                ulonglong2 A0 = *(const ulonglong2*)(arow);                     \
                ap[0] = A0.x; ap[1] = A0.y;                                     \
            }                                                                   \
            if ((MSTART) < 4) {                                                 \
                ulonglong2 A1 = *(const ulonglong2*)(arow + 4);                 \
                ap[2] = A1.x; ap[3] = A1.y;                                     \
            }                                                                   \
            if ((MSTART) < 6) {                                                 \
                ulonglong2 A2 = *(const ulonglong2*)(arow + 8);                 \
                ap[4] = A2.x; ap[5] = A2.y;                                     \
            }                                                                   \
            {                                                                   \
                ulonglong2 A3 = *(const ulonglong2*)(arow + 12);                \
                ap[6] = A3.x; ap[7] = A3.y;                                     \
            }                                                                   \
            _Pragma("unroll")                                                   \
            for (int m = (MSTART); m < 8; m++) {                                \
                ffma2(acc[m][0], ap[m], X.x); ffma2(acc[m][1], ap[m], X.y);     \
            }                                                                   \
        }

        // block 0: k = 0..riq (warp-uniform trip), all rows
        #pragma unroll 1
        for (int k = 0; k <= riq; k++) P3_ACCK(k, 0);

        // KBLOCK(MB): 8 k's in [riq+8(MB-1)+1, riq+8MB], rows m >= MB
        #define P3_KBLOCK(MB)                                                   \
        {                                                                       \
            const int kbase = riq + 8 * ((MB) - 1) + 1;                         \
            _Pragma("unroll")                                                   \
            for (int kk = 0; kk < 8; kk++) P3_ACCK(kbase + kk, MB);             \
        }
        P3_KBLOCK(1) P3_KBLOCK(2) P3_KBLOCK(3) P3_KBLOCK(4)
        P3_KBLOCK(5) P3_KBLOCK(6) P3_KBLOCK(7)
        #undef P3_KBLOCK
        #undef P3_ACCK

        __syncthreads();   // (A) everyone done reading xs

        // store new state (16B lane stride -> conflict-free)
        #pragma unroll
        for (int m = 0; m < 8; m++)
            *(ulonglong2*)&xs[(riq + 8 * m) * BS3 + bq] =
                make_ulonglong2(acc[m][0], acc[m][1]);
        // stage next A,B into the other buffer
        if (t < TCH - 1)
            p3_stage_AB(Ad + (cur ^ 1) * (NORD * P3_DPAD),
                        Bsd + (cur ^ 1) * (2 * NORD), apf, bpf, tid);
        __syncthreads();   // (B) state + staged A visible

        // copy out x_t: thread = (bcol, ihalf); 8 contiguous STG.128 per thread
        {
            const int bcol = tid & 127, ihalf = tid >> 7;
            float* op = out + ((size_t)(t0 + t) * BATCH + b0 + bcol) * NORD + ihalf * 32;
            const float* col = xs + bcol;
            #pragma unroll
            for (int i4 = 0; i4 < 8; i4++) {
                float4 v = make_float4(col[(ihalf * 32 + 4 * i4 + 0) * BS3],
                                       col[(ihalf * 32 + 4 * i4 + 1) * BS3],
                                       col[(ihalf * 32 + 4 * i4 + 2) * BS3],
                                       col[(ihalf * 32 + 4 * i4 + 3) * BS3]);
                *(float4*)(op + 4 * i4) = v;
            }
        }
        ucur = unxt;
        cur ^= 1;
    }
}

// ---------------------------------------------------------------------------
extern "C" void kernel_launch(void* const* d_in, const int* in_sizes, int n_in,
                              void* d_out, int out_size)
{
    const float* inp = (const float*)d_in[0];   // (L, BATCH)
    const float* A   = (const float*)d_in[1];   // (L, N, N)
    const float* Bv  = (const float*)d_in[2];   // (L, N)
    float* out = (float*)d_out;                 // (L, BATCH, N)

    cudaFuncSetAttribute(phase1_kernel, cudaFuncAttributeMaxDynamicSharedMemorySize, P1_SMEM);
    cudaFuncSetAttribute(phase3_kernel, cudaFuncAttributeMaxDynamicSharedMemorySize, P3_SMEM);

    phase1_kernel<<<CCH, 256, P1_SMEM>>>(A, Bv, inp);
    phase2_kernel<<<BATCH / 4, 256>>>();
    phase3_kernel<<<CCH * 2, 256, P3_SMEM>>>(A, Bv, inp, out);
}

// round 15
// speedup vs baseline: 1.0170x; 1.0170x over previous
#include <cuda_runtime.h>
#include <cstdint>

#define L_SEQ 4096
#define BATCH 256
#define NORD  64
#define TCH   32
#define CCH   128   // L_SEQ / TCH
#define BS3   64    // batch quarter per phase-3 CTA

typedef unsigned long long ull;

__device__ __forceinline__ ull bcast2(float a) {
    ull r; asm("mov.b64 %0, {%1, %1};" : "=l"(r) : "f"(a)); return r;
}
__device__ __forceinline__ void ffma2(ull &d, ull a, ull b) {
    asm("fma.rn.f32x2 %0, %1, %2, %0;" : "+l"(d) : "l"(a), "l"(b));
}
__device__ __forceinline__ float2 unpack2(ull v) {
    float2 f; asm("mov.b64 {%0, %1}, %2;" : "=f"(f.x), "=f"(f.y) : "l"(v)); return f;
}

// Scratch (static device globals: no allocations allowed)
__device__ float g_P[(size_t)CCH * NORD * NORD];   // [c][i][j]  row-major P_c   2 MB
__device__ float g_S[(size_t)CCH * BATCH * NORD];  // [c][b][i]  chunk sources   8 MB
__device__ float g_X[(size_t)CCH * BATCH * NORD];  // [c][b][i]  boundary states 8 MB

// ---------------------------------------------------------------------------
// Phase 1 (round-9 version, measured ~96us)
// ---------------------------------------------------------------------------
__global__ __launch_bounds__(256) void phase1_kernel(
    const float* __restrict__ A, const float* __restrict__ Bv,
    const float* __restrict__ inp)
{
    __shared__ float Pt[NORD * NORD];
    __shared__ float As[NORD * NORD];
    __shared__ float Bs[NORD];
    __shared__ float W[TCH][NORD];

    const int c = blockIdx.x, tid = threadIdx.x;
    const int t0 = c * TCH;
    const int ri = (tid & 15) * 4;   // i-tile
    const int cj = (tid >> 4) * 4;   // j-tile

    for (int idx = tid; idx < NORD * NORD; idx += 256)
        Pt[idx] = ((idx >> 6) == (idx & 63)) ? 1.f : 0.f;
    {
        const float4* A4 = (const float4*)(A + (size_t)(t0 + TCH - 1) * (NORD * NORD));
        float4* As4 = (float4*)As;
        #pragma unroll
        for (int q = 0; q < 4; q++) As4[tid + q * 256] = A4[tid + q * 256];
        if (tid < 16)
            ((float4*)Bs)[tid] = ((const float4*)(Bv + (size_t)(t0 + TCH - 1) * NORD))[tid];
    }
    __syncthreads();

    #pragma unroll 1
    for (int t = TCH - 1; t >= 0; --t) {
        float4 apf0, apf1, apf2, apf3, bpf;
        if (t > 0) {
            const float4* An = (const float4*)(A + (size_t)(t0 + t - 1) * (NORD * NORD));
            apf0 = An[tid]; apf1 = An[tid + 256]; apf2 = An[tid + 512]; apf3 = An[tid + 768];
            if (tid < 16) bpf = ((const float4*)(Bv + (size_t)(t0 + t - 1) * NORD))[tid];
        }

        float w0 = 0.f, w1 = 0.f, w2 = 0.f, w3 = 0.f;
        if (tid < NORD) {
            #pragma unroll
            for (int k4 = 0; k4 < 16; k4++) {
                w0 += Pt[(4 * k4 + 0) * NORD + tid] * Bs[4 * k4 + 0];
                w1 += Pt[(4 * k4 + 1) * NORD + tid] * Bs[4 * k4 + 1];
                w2 += Pt[(4 * k4 + 2) * NORD + tid] * Bs[4 * k4 + 2];
                w3 += Pt[(4 * k4 + 3) * NORD + tid] * Bs[4 * k4 + 3];
            }
        }

        ull acc2[4][2];
        #pragma unroll
        for (int jj = 0; jj < 4; jj++) { acc2[jj][0] = 0ull; acc2[jj][1] = 0ull; }

        #pragma unroll 8
        for (int k = 0; k < NORD; k++) {
            ulonglong2 p = *(const ulonglong2*)&Pt[k * NORD + ri];
            float4 a = *(const float4*)&As[k * NORD + cj];
            ull b0 = bcast2(a.x), b1 = bcast2(a.y), b2 = bcast2(a.z), b3 = bcast2(a.w);
            ffma2(acc2[0][0], b0, p.x); ffma2(acc2[0][1], b0, p.y);
            ffma2(acc2[1][0], b1, p.x); ffma2(acc2[1][1], b1, p.y);
            ffma2(acc2[2][0], b2, p.x); ffma2(acc2[2][1], b2, p.y);
            ffma2(acc2[3][0], b3, p.x); ffma2(acc2[3][1], b3, p.y);
        }
        __syncthreads();

        if (tid < NORD) W[t][tid] = (w0 + w1) + (w2 + w3);
        if (t > 0) {
            #pragma unroll
            for (int jj = 0; jj < 4; jj++)
                *(ulonglong2*)&Pt[(cj + jj) * NORD + ri] =
                    make_ulonglong2(acc2[jj][0], acc2[jj][1]);
            float4* As4 = (float4*)As;
            As4[tid] = apf0; As4[tid + 256] = apf1; As4[tid + 512] = apf2; As4[tid + 768] = apf3;
            if (tid < 16) ((float4*)Bs)[tid] = bpf;
        } else {
            float f[4][4];
            #pragma unroll
            for (int jj = 0; jj < 4; jj++) {
                float2 v0 = unpack2(acc2[jj][0]); f[jj][0] = v0.x; f[jj][1] = v0.y;
                float2 v1 = unpack2(acc2[jj][1]); f[jj][2] = v1.x; f[jj][3] = v1.y;
            }
            float* gp = g_P + (size_t)c * (NORD * NORD);
            #pragma unroll
            for (int ii = 0; ii < 4; ii++)
                *(float4*)&gp[(ri + ii) * NORD + cj] =
                    make_float4(f[0][ii], f[1][ii], f[2][ii], f[3][ii]);
        }
        __syncthreads();
    }

    {
        float u[TCH];
        #pragma unroll
        for (int tt = 0; tt < TCH; tt++) u[tt] = inp[(size_t)(t0 + tt) * BATCH + tid];
        float* sp = g_S + ((size_t)c * BATCH + tid) * NORD;
        #pragma unroll
        for (int half = 0; half < 2; half++) {
            ull acc[16];
            #pragma unroll
            for (int m = 0; m < 16; m++) acc[m] = 0ull;
            #pragma unroll 4
            for (int tt = 0; tt < TCH; tt++) {
                ull ub = bcast2(u[tt]);
                const ull* wrow = (const ull*)&W[tt][half * 32];
                #pragma unroll
                for (int m = 0; m < 16; m++) ffma2(acc[m], ub, wrow[m]);
            }
            #pragma unroll
            for (int m2 = 0; m2 < 8; m2++)
                *(ulonglong2*)&sp[half * 32 + m2 * 4] =
                    make_ulonglong2(acc[2 * m2], acc[2 * m2 + 1]);
        }
    }
}

// ---------------------------------------------------------------------------
// Phase 2 (unchanged): X_c = P_c @ X_{c-1} + S_c
// ---------------------------------------------------------------------------
#define P2PAD 68
__global__ __launch_bounds__(256) void phase2_kernel()
{
    __shared__ float Ps[2][NORD * P2PAD];
    __shared__ float xsm[2][4][NORD];

    const int tid = threadIdx.x;
    const int b0 = blockIdx.x * 4;
    const int i  = tid >> 2;
    const int bb = tid & 3;

    {
        const float4* gp = (const float4*)g_P;
        #pragma unroll
        for (int q = 0; q < 4; q++) {
            int f = tid + q * 256;
            int ii = f >> 4, j4 = f & 15;
            *(float4*)&Ps[0][ii * P2PAD + j4 * 4] = gp[f];
        }
        xsm[0][bb][i] = 0.f;
    }
    float s_cur = g_S[((size_t)b0 + bb) * NORD + i];
    __syncthreads();

    int cur = 0;
    #pragma unroll 1
    for (int c = 0; c < CCH; c++) {
        float4 pf0, pf1, pf2, pf3; float s_nxt = 0.f;
        if (c + 1 < CCH) {
            const float4* gp = (const float4*)(g_P + (size_t)(c + 1) * (NORD * NORD));
            pf0 = gp[tid]; pf1 = gp[tid + 256]; pf2 = gp[tid + 512]; pf3 = gp[tid + 768];
            s_nxt = g_S[((size_t)(c + 1) * BATCH + b0 + bb) * NORD + i];
        }

        ull a0 = 0ull, a1 = 0ull, a2 = 0ull, a3 = 0ull;
        const float* prow = &Ps[cur][i * P2PAD];
        const float* xrow = &xsm[cur][bb][0];
        #pragma unroll
        for (int j8 = 0; j8 < 8; j8++) {
            ulonglong2 p0 = *(const ulonglong2*)(prow + j8 * 8);
            ulonglong2 p1 = *(const ulonglong2*)(prow + j8 * 8 + 4);
            ulonglong2 x0 = *(const ulonglong2*)(xrow + j8 * 8);
            ulonglong2 x1 = *(const ulonglong2*)(xrow + j8 * 8 + 4);
            ffma2(a0, p0.x, x0.x); ffma2(a1, p0.y, x0.y);
            ffma2(a2, p1.x, x1.x); ffma2(a3, p1.y, x1.y);
        }
        float2 f0 = unpack2(a0), f1 = unpack2(a1), f2 = unpack2(a2), f3 = unpack2(a3);
        float acc = s_cur + ((f0.x + f0.y) + (f1.x + f1.y)) + ((f2.x + f2.y) + (f3.x + f3.y));

        const int nxt = cur ^ 1;
        xsm[nxt][bb][i] = acc;
        g_X[((size_t)c * BATCH + b0 + bb) * NORD + i] = acc;
        if (c + 1 < CCH) {
            #pragma unroll
            for (int q = 0; q < 4; q++) {
                float4 pv = (q == 0) ? pf0 : (q == 1) ? pf1 : (q == 2) ? pf2 : pf3;
                int f = tid + q * 256;
                int ii = f >> 4, j4 = f & 15;
                *(float4*)&Ps[nxt][ii * P2PAD + j4 * 4] = pv;
            }
        }
        s_cur = s_nxt;
        __syncthreads();
        cur = nxt;
    }
}

// ---------------------------------------------------------------------------
// Phase 3: 4 CTAs per chunk (batch quarters of 64), 256 threads,
// __launch_bounds__(256,4) + single-buffered A/B (34 KB smem) ->
// ~3.5 CTAs/SM = ~28 warps/SM for latency hiding; grid=512 = one wave.
// Thread (riq = tid>>5 warp-uniform, bq = 2*(tid&31)) owns rows {riq+8m}
// (interleaved) x 2 batches (one FFMA2 pair).  A staged PERMUTED:
//   As[k][(i&7)*8 + (i>>3)] = A[i][k]  -> warp's 8 rows contiguous,
//   2 broadcast LDS.128 per k.  Lower-triangular A: warp-uniform k-blocks.
// Single-buffer A is safe: barrier (A) ends all reads of As before restage,
// barrier (B) publishes the restage before the next step's reads.
// ---------------------------------------------------------------------------
#define P3_APAD 68

__device__ __forceinline__ void p3_stage_AB(float* As, float* Bs,
                                            const float4* apf, float4 bpf, int tid) {
    #pragma unroll
    for (int q = 0; q < 4; q++) {
        int f = tid + q * 256;              // float4 idx: i = f>>4, j = 4*(f&15)
        int i = f >> 4, j0 = (f & 15) * 4;
        int p = ((i & 7) << 3) | (i >> 3);  // permuted row position
        float4 v = apf[q];
        As[(j0 + 0) * P3_APAD + p] = v.x;
        As[(j0 + 1) * P3_APAD + p] = v.y;
        As[(j0 + 2) * P3_APAD + p] = v.z;
        As[(j0 + 3) * P3_APAD + p] = v.w;
    }
    if (tid < 16) {
        #pragma unroll
        for (int r = 0; r < 4; r++) {
            int i = 4 * tid + r;
            float v = (r == 0) ? bpf.x : (r == 1) ? bpf.y : (r == 2) ? bpf.z : bpf.w;
            Bs[((i & 7) << 3) | (i >> 3)] = v;
        }
    }
}

__global__ __launch_bounds__(256, 4) void phase3_kernel(
    const float* __restrict__ A, const float* __restrict__ Bv,
    const float* __restrict__ inp, float* __restrict__ out)
{
    __shared__ float As[NORD * P3_APAD];   // [64][68] permuted A (single buffer)
    __shared__ float xs[NORD * BS3];       // [64][64] xs[j][b]
    __shared__ float Bs[NORD];             // permuted B

    const int tid = threadIdx.x;
    const int c   = blockIdx.x >> 2;
    const int b0  = (blockIdx.x & 3) * BS3;
    const int t0  = c * TCH;
    const int riq = tid >> 5;              // warp-uniform row offset 0..7
    const int bq  = (tid & 31) * 2;        // 2 batches per thread

    // stage A,B for t=0; load u for t=0
    {
        const float4* A4 = (const float4*)(A + (size_t)t0 * (NORD * NORD));
        float4 apf[4];
        #pragma unroll
        for (int q = 0; q < 4; q++) apf[q] = A4[tid + q * 256];
        float4 bpf = make_float4(0.f, 0.f, 0.f, 0.f);
        if (tid < 16) bpf = ((const float4*)(Bv + (size_t)t0 * NORD))[tid];
        p3_stage_AB(As, Bs, apf, bpf, tid);
    }
    ull ucur = *(const ull*)(inp + (size_t)t0 * BATCH + b0 + bq);

    // load initial state into xs[j][b]: thread = (bcol = tid&63, jq = tid>>6)
    {
        const int bcol = tid & 63, jq = tid >> 6;   // jq in 0..3 -> 16 j's each
        if (c == 0) {
            #pragma unroll
            for (int j = 0; j < 16; j++) xs[(jq * 16 + j) * BS3 + bcol] = 0.f;
        } else {
            const float4* Xp = (const float4*)(g_X + (((size_t)(c - 1)) * BATCH + b0 + bcol) * NORD + jq * 16);
            #pragma unroll
            for (int j4 = 0; j4 < 4; j4++) {
                float4 v = Xp[j4];
                xs[(jq * 16 + 4 * j4 + 0) * BS3 + bcol] = v.x;
                xs[(jq * 16 + 4 * j4 + 1) * BS3 + bcol] = v.y;
                xs[(jq * 16 + 4 * j4 + 2) * BS3 + bcol] = v.z;
                xs[(jq * 16 + 4 * j4 + 3) * BS3 + bcol] = v.w;
            }
        }
    }
    __syncthreads();

    #pragma unroll 1
    for (int t = 0; t < TCH; t++) {
        // prefetch next A,B,u into registers
        float4 apf[4]; float4 bpf; ull unxt;
        if (t < TCH - 1) {
            const float4* An = (const float4*)(A + (size_t)(t0 + t + 1) * (NORD * NORD));
            #pragma unroll
            for (int q = 0; q < 4; q++) apf[q] = An[tid + q * 256];
            if (tid < 16) bpf = ((const float4*)(Bv + (size_t)(t0 + t + 1) * NORD))[tid];
            unxt = *(const ull*)(inp + (size_t)(t0 + t + 1) * BATCH + b0 + bq);
        }

        // init acc[m] = B[row]*u
        ull acc[8];
        {
            float4 B0 = *(const float4*)&Bs[riq * 8];
            float4 B1 = *(const float4*)&Bs[riq * 8 + 4];
            float bb[8] = {B0.x, B0.y, B0.z, B0.w, B1.x, B1.y, B1.z, B1.w};
            #pragma unroll
            for (int m = 0; m < 8; m++) {
                ull ab = bcast2(bb[m]);
                acc[m] = 0ull;
                ffma2(acc[m], ab, ucur);
            }
        }

        // triangular MACs: row riq+8m active for k <= riq+8m
        #define P3_ACCK(K, MSTART)                                              \
        {                                                                       \
            ull X = *(const ull*)&xs[(K) * BS3 + bq];                           \
            float a[8];                                                         \
            if ((MSTART) < 4) {                                                 \
                float4 A0 = *(const float4*)&As[(K) * P3_APAD + riq * 8];       \
                a[0] = A0.x; a[1] = A0.y; a[2] = A0.z; a[3] = A0.w;             \
            }                                                                   \
            {                                                                   \
                float4 A1 = *(const float4*)&As[(K) * P3_APAD + riq * 8 + 4];   \
                a[4] = A1.x; a[5] = A1.y; a[6] = A1.z; a[7] = A1.w;             \
            }                                                                   \
            _Pragma("unroll")                                                   \
            for (int m = (MSTART); m < 8; m++) {                                \
                ull ab = bcast2(a[m]);                                          \
                ffma2(acc[m], ab, X);                                           \
            }                                                                   \
        }

        // block 0: k = 0..riq (warp-uniform trip), all rows
        #pragma unroll 1
        for (int k = 0; k <= riq; k++) P3_ACCK(k, 0);

        // KBLOCK(MB): 8 k's in [riq+8(MB-1)+1, riq+8MB], rows m >= MB
        #define P3_KBLOCK(MB)                                                   \
        {                                                                       \
            const int kbase = riq + 8 * ((MB) - 1) + 1;                         \
            _Pragma("unroll")                                                   \
            for (int kk = 0; kk < 8; kk++) P3_ACCK(kbase + kk, MB);             \
        }
        P3_KBLOCK(1) P3_KBLOCK(2) P3_KBLOCK(3) P3_KBLOCK(4)
        P3_KBLOCK(5) P3_KBLOCK(6) P3_KBLOCK(7)
        #undef P3_KBLOCK
        #undef P3_ACCK

        __syncthreads();   // (A) everyone done reading xs AND As/Bs

        // store new state (8B lane stride -> conflict-free)
        #pragma unroll
        for (int m = 0; m < 8; m++)
            *(ull*)&xs[(riq + 8 * m) * BS3 + bq] = acc[m];
        // restage A,B into the SAME buffer (reads all finished at barrier A)
        if (t < TCH - 1)
            p3_stage_AB(As, Bs, apf, bpf, tid);
        __syncthreads();   // (B) state + restaged A visible

        // copy out x_t: thread = (bcol = tid&63, iq = tid>>6); 4x STG.128
        {
            const int bcol = tid & 63, iq = tid >> 6;
            float* op = out + ((size_t)(t0 + t) * BATCH + b0 + bcol) * NORD + iq * 16;
            const float* col = xs + bcol;
            #pragma unroll
            for (int i4 = 0; i4 < 4; i4++) {
                float4 v = make_float4(col[(iq * 16 + 4 * i4 + 0) * BS3],
                                       col[(iq * 16 + 4 * i4 + 1) * BS3],
                                       col[(iq * 16 + 4 * i4 + 2) * BS3],
                                       col[(iq * 16 + 4 * i4 + 3) * BS3]);
                *(float4*)(op + 4 * i4) = v;
            }
        }
        ucur = unxt;
    }
}

// ---------------------------------------------------------------------------
extern "C" void kernel_launch(void* const* d_in, const int* in_sizes, int n_in,
                              void* d_out, int out_size)
{
    const float* inp = (const float*)d_in[0];   // (L, BATCH)
    const float* A   = (const float*)d_in[1];   // (L, N, N)
    const float* Bv  = (const float*)d_in[2];   // (L, N)
    float* out = (float*)d_out;                 // (L, BATCH, N)

    phase1_kernel<<<CCH, 256>>>(A, Bv, inp);
    phase2_kernel<<<BATCH / 4, 256>>>();
    phase3_kernel<<<CCH * 4, 256>>>(A, Bv, inp, out);
}